// round 4
// baseline (speedup 1.0000x reference)
#include <cuda_runtime.h>
#include <cuda_fp16.h>
#include <cstdint>

// ============================================================================
// Fused attention block via mma.sync (HMMA). fp32 accuracy via fp16 hi/lo
// split (3-term Markidis for precision-critical GEMMs; 2-term for ctx).
// 4-stage cp.async pipeline, one __syncthreads per K-iteration.
// B=4, S=2048, D=1024.
// ============================================================================

#define TOK 8192
#define DIM 1024
#define SEQ 2048
#define BATCH 4

static const long long OUT_ELEMS = (long long)TOK * DIM;
static const long long PATTN_ELEMS = (long long)BATCH * SEQ * SEQ;

// ---------------- device scratch ----------------
__device__ __half g_xhi[TOK * DIM], g_xlo[TOK * DIM];
__device__ __half g_wqThi[DIM * DIM], g_wqTlo[DIM * DIM];
__device__ __half g_wkThi[DIM * DIM], g_wkTlo[DIM * DIM];
__device__ __half g_wvThi[DIM * DIM], g_wvTlo[DIM * DIM];
__device__ __half g_wpThi[DIM * DIM], g_wpTlo[DIM * DIM];
__device__ __half g_qhi[TOK * DIM], g_qlo[TOK * DIM];
__device__ __half g_khi[TOK * DIM], g_klo[TOK * DIM];
__device__ float  g_v[TOK * DIM];
__device__ __half g_vThi[TOK * DIM], g_vTlo[TOK * DIM];   // [B][DIM][SEQ]
__device__ __half g_phi[BATCH * SEQ * SEQ];
__device__ __half g_ctxhi[TOK * DIM], g_ctxlo[TOK * DIM];
__device__ float  g_scores_fb[BATCH * SEQ * SEQ];

// ---------------- PTX helpers ----------------
__device__ __forceinline__ uint32_t smem_u32_f(const void* p) {
    uint32_t a;
    asm("{ .reg .u64 t; cvta.to.shared.u64 t, %1; cvt.u32.u64 %0, t; }"
        : "=r"(a) : "l"(p));
    return a;
}
__device__ __forceinline__ void cp16(uint32_t dst, const void* src) {
    asm volatile("cp.async.cg.shared.global [%0], [%1], 16;" :: "r"(dst), "l"(src));
}
__device__ __forceinline__ void cp_commit() { asm volatile("cp.async.commit_group;"); }
template <int N>
__device__ __forceinline__ void cp_wait() {
    asm volatile("cp.async.wait_group %0;" :: "n"(N));
}
__device__ __forceinline__ void ldm_x4(uint32_t r[4], uint32_t addr) {
    asm volatile("ldmatrix.sync.aligned.m8n8.x4.shared.b16 {%0,%1,%2,%3}, [%4];"
                 : "=r"(r[0]), "=r"(r[1]), "=r"(r[2]), "=r"(r[3]) : "r"(addr));
}
__device__ __forceinline__ void mma16816(float c[4], const uint32_t a[4],
                                         const uint32_t b0, const uint32_t b1) {
    asm volatile(
        "mma.sync.aligned.m16n8k16.row.col.f32.f16.f16.f32 "
        "{%0,%1,%2,%3},{%4,%5,%6,%7},{%8,%9},{%0,%1,%2,%3};"
        : "+f"(c[0]), "+f"(c[1]), "+f"(c[2]), "+f"(c[3])
        : "r"(a[0]), "r"(a[1]), "r"(a[2]), "r"(a[3]), "r"(b0), "r"(b1));
}

// smem tile geometry: 128 rows x 32 halfs, row pitch 80B (64B data + 16B pad)
#define PITCH 80u
#define TILE_B (128u * PITCH)            // 10240 B
#define T_AH 0u
#define T_AL TILE_B
#define T_BH (2u * TILE_B)
#define T_BL (3u * TILE_B)
#define STG  (4u * TILE_B)               // 40960 B per stage
#define NSTAGE 4
#define SMEM_DYN (NSTAGE * 4 * 10240)    // 163840 B

// ============================================================================
// MMA GEMM: C[M,N] = alpha * (Ah[+Al])[M,K] @ (Bh+Bl)[N,K]^T (+bias)
// Block tile 128x128, BK=32, 256 threads (8 warps, 4(m) x 2(n) warp grid).
// ASPLIT: 3-term (ah*bh + al*bh + ah*bl); else 2-term (ah*bh + ah*bl).
// ============================================================================
template <bool ASPLIT, bool WF32, bool HASBIAS>
__global__ void __launch_bounds__(256) mma_gemm(
    const __half* __restrict__ Ah_g, const __half* __restrict__ Al_g,
    const __half* __restrict__ Bh_g, const __half* __restrict__ Bl_g,
    const float* __restrict__ bias,
    float* __restrict__ Cf, __half* __restrict__ Chi, __half* __restrict__ Clo,
    int N, int K, float alpha,
    long long sA, long long sB, long long sC)
{
    extern __shared__ char smem_raw[];
    const uint32_t base = smem_u32_f(smem_raw);

    const int tid = threadIdx.x;
    const int warp = tid >> 5, lane = tid & 31;
    const long long zb = blockIdx.z;
    const __half* Ah = Ah_g + zb * sA;
    const __half* Al = ASPLIT ? (Al_g + zb * sA) : nullptr;
    const __half* Bh = Bh_g + zb * sB;
    const __half* Bl = Bl_g + zb * sB;

    const int row0 = blockIdx.y * 128;
    const int col0 = blockIdx.x * 128;

    const int r_ld = tid >> 2;
    const int q_ld = tid & 3;
    long long aOff[2], bOff[2];
    uint32_t dOff[2];
#pragma unroll
    for (int j = 0; j < 2; j++) {
        int r = r_ld + j * 64;
        aOff[j] = (long long)(row0 + r) * K + q_ld * 8;
        bOff[j] = (long long)(col0 + r) * K + q_ld * 8;
        dOff[j] = (uint32_t)r * PITCH + (uint32_t)q_ld * 16u;
    }

    const int wm = warp & 3, wn = warp >> 2;
    const int m0 = wm * 32, n0 = wn * 64;
    const uint32_t aLane = (uint32_t)(lane & 15) * PITCH + (uint32_t)(lane >> 4) * 16u;
    const uint32_t bLane = (uint32_t)((lane & 7) + ((lane >> 4) << 3)) * PITCH +
                           (uint32_t)((lane >> 3) & 1) * 16u;

    float acc[2][8][4];
#pragma unroll
    for (int i = 0; i < 2; i++)
#pragma unroll
        for (int j = 0; j < 8; j++)
#pragma unroll
            for (int e = 0; e < 4; e++) acc[i][j][e] = 0.f;

    const int nk = K >> 5;   // BK = 32; nk >= 16 always here

    // prologue: stages 0..2
#pragma unroll
    for (int s = 0; s < NSTAGE - 1; s++) {
        uint32_t sb = base + (uint32_t)s * STG;
        long long k0 = (long long)s * 32;
#pragma unroll
        for (int j = 0; j < 2; j++) {
            cp16(sb + T_AH + dOff[j], Ah + aOff[j] + k0);
            if (ASPLIT) cp16(sb + T_AL + dOff[j], Al + aOff[j] + k0);
            cp16(sb + T_BH + dOff[j], Bh + bOff[j] + k0);
            cp16(sb + T_BL + dOff[j], Bl + bOff[j] + k0);
        }
        cp_commit();
    }

    for (int i = 0; i < nk; i++) {
        // wait for stage i to land (younger pending groups: min(2, nk-1-i))
        if (i + 2 < nk)      cp_wait<2>();
        else if (i + 1 < nk) cp_wait<1>();
        else                 cp_wait<0>();
        __syncthreads();   // also fences compute(i-1) before refilling its slot

        if (i + NSTAGE - 1 < nk) {
            uint32_t sb = base + (uint32_t)((i + NSTAGE - 1) & (NSTAGE - 1)) * STG;
            long long k0 = (long long)(i + NSTAGE - 1) * 32;
#pragma unroll
            for (int j = 0; j < 2; j++) {
                cp16(sb + T_AH + dOff[j], Ah + aOff[j] + k0);
                if (ASPLIT) cp16(sb + T_AL + dOff[j], Al + aOff[j] + k0);
                cp16(sb + T_BH + dOff[j], Bh + bOff[j] + k0);
                cp16(sb + T_BL + dOff[j], Bl + bOff[j] + k0);
            }
            cp_commit();
        }

        const uint32_t sb = base + (uint32_t)(i & (NSTAGE - 1)) * STG;
#pragma unroll
        for (int ks = 0; ks < 2; ks++) {
            const uint32_t kb = (uint32_t)ks * 32u;
            uint32_t ah[2][4], al[2][4], bh[4][4], bl[4][4];
#pragma unroll
            for (int mf = 0; mf < 2; mf++) {
                uint32_t ro = (uint32_t)(m0 + mf * 16) * PITCH + kb + aLane;
                ldm_x4(ah[mf], sb + T_AH + ro);
                if (ASPLIT) ldm_x4(al[mf], sb + T_AL + ro);
            }
#pragma unroll
            for (int q = 0; q < 4; q++) {
                uint32_t ro = (uint32_t)(n0 + q * 16) * PITCH + kb + bLane;
                ldm_x4(bh[q], sb + T_BH + ro);
                ldm_x4(bl[q], sb + T_BL + ro);
            }
#pragma unroll
            for (int mf = 0; mf < 2; mf++)
#pragma unroll
                for (int nf = 0; nf < 8; nf++) {
                    const int q = nf >> 1, h = (nf & 1) * 2;
                    mma16816(acc[mf][nf], ah[mf], bh[q][h], bh[q][h + 1]);
                    if (ASPLIT) mma16816(acc[mf][nf], al[mf], bh[q][h], bh[q][h + 1]);
                    mma16816(acc[mf][nf], ah[mf], bl[q][h], bl[q][h + 1]);
                }
        }
    }

    // ---- epilogue ----
    const int tg = lane >> 2, tl = lane & 3;
#pragma unroll
    for (int mf = 0; mf < 2; mf++) {
#pragma unroll
        for (int nf = 0; nf < 8; nf++) {
            const int col = col0 + n0 + nf * 8 + tl * 2;
            float b0 = 0.f, b1 = 0.f;
            if (HASBIAS) { b0 = __ldg(bias + col); b1 = __ldg(bias + col + 1); }
#pragma unroll
            for (int hrow = 0; hrow < 2; hrow++) {
                const int row = row0 + m0 + mf * 16 + tg + hrow * 8;
                float v0 = acc[mf][nf][hrow * 2 + 0] * alpha + b0;
                float v1 = acc[mf][nf][hrow * 2 + 1] * alpha + b1;
                const long long off = zb * sC + (long long)row * N + col;
                if (WF32) {
                    float2 o; o.x = v0; o.y = v1;
                    *(float2*)(Cf + off) = o;
                } else {
                    __half h0 = __float2half_rn(v0);
                    __half h1 = __float2half_rn(v1);
                    __half2 th; th.x = h0; th.y = h1;
                    __half2 tlh;
                    tlh.x = __float2half_rn(v0 - __half2float(h0));
                    tlh.y = __float2half_rn(v1 - __half2float(h1));
                    *(__half2*)(Chi + off) = th;
                    *(__half2*)(Clo + off) = tlh;
                }
            }
        }
    }
}

// ============================================================================
// helper kernels
// ============================================================================
__global__ void __launch_bounds__(256) convert_split_kernel(
    const float* __restrict__ in, __half* __restrict__ hi,
    __half* __restrict__ lo, long long n4)
{
    long long i = (long long)blockIdx.x * 256 + threadIdx.x;
    if (i >= n4) return;
    float4 v = ((const float4*)in)[i];
    __half h0 = __float2half_rn(v.x), h1 = __float2half_rn(v.y);
    __half h2 = __float2half_rn(v.z), h3 = __float2half_rn(v.w);
    __half2 a, b; a.x = h0; a.y = h1; b.x = h2; b.y = h3;
    ((__half2*)hi)[i * 2 + 0] = a;
    ((__half2*)hi)[i * 2 + 1] = b;
    __half2 c, d;
    c.x = __float2half_rn(v.x - __half2float(h0));
    c.y = __float2half_rn(v.y - __half2float(h1));
    d.x = __float2half_rn(v.z - __half2float(h2));
    d.y = __float2half_rn(v.w - __half2float(h3));
    ((__half2*)lo)[i * 2 + 0] = c;
    ((__half2*)lo)[i * 2 + 1] = d;
}

__global__ void __launch_bounds__(256) transpose_split_kernel(
    const float* __restrict__ in, __half* __restrict__ hi,
    __half* __restrict__ lo, int R, int C,
    long long sIn, long long sOut)
{
    __shared__ float t[32][33];
    const float* src = in + (long long)blockIdx.z * sIn;
    const int c0 = blockIdx.x * 32, r0 = blockIdx.y * 32;
    const int tx = threadIdx.x & 31, ty = threadIdx.x >> 5;
#pragma unroll
    for (int j = 0; j < 4; j++)
        t[ty + j * 8][tx] = src[(long long)(r0 + ty + j * 8) * C + c0 + tx];
    __syncthreads();
#pragma unroll
    for (int j = 0; j < 4; j++) {
        int oc = c0 + ty + j * 8;
        float v = t[tx][ty + j * 8];
        long long o = (long long)blockIdx.z * sOut + (long long)oc * R + r0 + tx;
        __half h = __float2half_rn(v);
        hi[o] = h;
        lo[o] = __float2half_rn(v - __half2float(h));
    }
}

// softmax rows of 2048 (fp32 in place) + fp16 p_hi output
__global__ void __launch_bounds__(256) softmax2048_kernel(
    float* __restrict__ p, __half* __restrict__ phi)
{
    const long long roff = (long long)blockIdx.x * 2048;
    float* row = p + roff;
    const int tid = threadIdx.x;

    float4 v0 = ((const float4*)row)[tid];
    float4 v1 = ((const float4*)row)[tid + 256];

    float m = fmaxf(fmaxf(fmaxf(v0.x, v0.y), fmaxf(v0.z, v0.w)),
                    fmaxf(fmaxf(v1.x, v1.y), fmaxf(v1.z, v1.w)));
    __shared__ float red[8];
#pragma unroll
    for (int o = 16; o; o >>= 1) m = fmaxf(m, __shfl_xor_sync(0xffffffffu, m, o));
    if ((tid & 31) == 0) red[tid >> 5] = m;
    __syncthreads();
    m = red[0];
#pragma unroll
    for (int i = 1; i < 8; i++) m = fmaxf(m, red[i]);
    __syncthreads();

    v0.x = expf(v0.x - m); v0.y = expf(v0.y - m);
    v0.z = expf(v0.z - m); v0.w = expf(v0.w - m);
    v1.x = expf(v1.x - m); v1.y = expf(v1.y - m);
    v1.z = expf(v1.z - m); v1.w = expf(v1.w - m);

    float s = (v0.x + v0.y) + (v0.z + v0.w) + (v1.x + v1.y) + (v1.z + v1.w);
#pragma unroll
    for (int o = 16; o; o >>= 1) s += __shfl_xor_sync(0xffffffffu, s, o);
    if ((tid & 31) == 0) red[tid >> 5] = s;
    __syncthreads();
    s = ((red[0] + red[1]) + (red[2] + red[3])) +
        ((red[4] + red[5]) + (red[6] + red[7]));
    float inv = 1.0f / s;

    v0.x *= inv; v0.y *= inv; v0.z *= inv; v0.w *= inv;
    v1.x *= inv; v1.y *= inv; v1.z *= inv; v1.w *= inv;

    ((float4*)row)[tid] = v0;
    ((float4*)row)[tid + 256] = v1;

    const float vv[8] = {v0.x, v0.y, v0.z, v0.w, v1.x, v1.y, v1.z, v1.w};
    const long long off[2] = {roff + (long long)tid * 4,
                              roff + (long long)(tid + 256) * 4};
#pragma unroll
    for (int hseg = 0; hseg < 2; hseg++) {
#pragma unroll
        for (int g = 0; g < 2; g++) {
            float a = vv[hseg * 4 + g * 2], b = vv[hseg * 4 + g * 2 + 1];
            __half2 th;
            th.x = __float2half_rn(a);
            th.y = __float2half_rn(b);
            *(__half2*)(phi + off[hseg] + g * 2) = th;
        }
    }
}

// ============================================================================
// host launcher
// ============================================================================
extern "C" void kernel_launch(void* const* d_in, const int* in_sizes, int n_in,
                              void* d_out, int out_size)
{
    const float* x  = (const float*)d_in[0];
    const float* wq = (const float*)d_in[1];
    const float* bq = (const float*)d_in[2];
    const float* wk = (const float*)d_in[3];
    const float* bk = (const float*)d_in[4];
    const float* wv = (const float*)d_in[5];
    const float* bv = (const float*)d_in[6];
    const float* wp = (const float*)d_in[7];
    const float* bp = (const float*)d_in[8];
    float* out = (float*)d_out;

#define SYM(p, s) void* p##_; cudaGetSymbolAddress(&p##_, s);
    SYM(xhi, g_xhi) SYM(xlo, g_xlo)
    SYM(wqh, g_wqThi) SYM(wql, g_wqTlo)
    SYM(wkh, g_wkThi) SYM(wkl, g_wkTlo)
    SYM(wvh, g_wvThi) SYM(wvl, g_wvTlo)
    SYM(wph, g_wpThi) SYM(wpl, g_wpTlo)
    SYM(qhi, g_qhi) SYM(qlo, g_qlo)
    SYM(khi, g_khi) SYM(klo, g_klo)
    SYM(vf, g_v)
    SYM(vth, g_vThi) SYM(vtl, g_vTlo)
    SYM(phi, g_phi)
    SYM(cxh, g_ctxhi) SYM(cxl, g_ctxlo)
    SYM(sfb, g_scores_fb)
#undef SYM
#define HF(p) ((__half*)p##_)

    float* pattn = (out_size >= (long long)(OUT_ELEMS + PATTN_ELEMS))
                       ? (out + OUT_ELEMS) : (float*)sfb_;

    cudaFuncSetAttribute(mma_gemm<true,  false, true >, cudaFuncAttributeMaxDynamicSharedMemorySize, SMEM_DYN);
    cudaFuncSetAttribute(mma_gemm<true,  true,  true >, cudaFuncAttributeMaxDynamicSharedMemorySize, SMEM_DYN);
    cudaFuncSetAttribute(mma_gemm<true,  true,  false>, cudaFuncAttributeMaxDynamicSharedMemorySize, SMEM_DYN);
    cudaFuncSetAttribute(mma_gemm<false, false, false>, cudaFuncAttributeMaxDynamicSharedMemorySize, SMEM_DYN);

    // 1) split x
    convert_split_kernel<<<(TOK * DIM / 4 + 255) / 256, 256>>>(
        x, HF(xhi), HF(xlo), TOK * DIM / 4);

    // 2) transpose + split weights
    dim3 gW(DIM / 32, DIM / 32, 1);
    transpose_split_kernel<<<gW, 256>>>(wq, HF(wqh), HF(wql), DIM, DIM, 0, 0);
    transpose_split_kernel<<<gW, 256>>>(wk, HF(wkh), HF(wkl), DIM, DIM, 0, 0);
    transpose_split_kernel<<<gW, 256>>>(wv, HF(wvh), HF(wvl), DIM, DIM, 0, 0);
    transpose_split_kernel<<<gW, 256>>>(wp, HF(wph), HF(wpl), DIM, DIM, 0, 0);

    // 3) q, k projections (3-term) -> fp16 split outputs
    dim3 gProj(DIM / 128, TOK / 128, 1);
    mma_gemm<true, false, true><<<gProj, 256, SMEM_DYN>>>(
        HF(xhi), HF(xlo), HF(wqh), HF(wql), bq, nullptr, HF(qhi), HF(qlo),
        DIM, DIM, 1.f, 0, 0, 0);
    mma_gemm<true, false, true><<<gProj, 256, SMEM_DYN>>>(
        HF(xhi), HF(xlo), HF(wkh), HF(wkl), bk, nullptr, HF(khi), HF(klo),
        DIM, DIM, 1.f, 0, 0, 0);

    // 4) v projection (3-term) -> fp32, then transpose-split -> vT[b][d][t]
    mma_gemm<true, true, true><<<gProj, 256, SMEM_DYN>>>(
        HF(xhi), HF(xlo), HF(wvh), HF(wvl), bv, (float*)vf_, nullptr, nullptr,
        DIM, DIM, 1.f, 0, 0, 0);
    dim3 gVT(DIM / 32, SEQ / 32, BATCH);
    transpose_split_kernel<<<gVT, 256>>>((const float*)vf_, HF(vth), HF(vtl),
                                         SEQ, DIM,
                                         (long long)SEQ * DIM, (long long)DIM * SEQ);

    // 5) scores = 32 * q @ k^T (3-term) -> fp32 p_attn region
    dim3 gSc(SEQ / 128, SEQ / 128, BATCH);
    mma_gemm<true, true, false><<<gSc, 256, SMEM_DYN>>>(
        HF(qhi), HF(qlo), HF(khi), HF(klo), nullptr, pattn, nullptr, nullptr,
        SEQ, DIM, 32.f,
        (long long)SEQ * DIM, (long long)SEQ * DIM, (long long)SEQ * SEQ);

    // 6) softmax in place + fp16 p_hi
    softmax2048_kernel<<<TOK, 256>>>(pattn, HF(phi));

    // 7) ctx = p @ v (2-term: p_hi*(v_hi+v_lo)) -> fp16 split
    dim3 gCtx(DIM / 128, SEQ / 128, BATCH);
    mma_gemm<false, false, false><<<gCtx, 256, SMEM_DYN>>>(
        HF(phi), nullptr, HF(vth), HF(vtl), nullptr, nullptr, HF(cxh), HF(cxl),
        DIM, SEQ, 1.f,
        (long long)SEQ * SEQ, (long long)DIM * SEQ, (long long)SEQ * DIM);

    // 8) out = ctx @ wp + bp (3-term)
    mma_gemm<true, true, true><<<gProj, 256, SMEM_DYN>>>(
        HF(cxh), HF(cxl), HF(wph), HF(wpl), bp, out, nullptr, nullptr,
        DIM, DIM, 1.f, 0, 0, 0);
}

// round 5
// speedup vs baseline: 1.2346x; 1.2346x over previous
#include <cuda_runtime.h>
#include <cuda_fp16.h>
#include <cstdint>

// ============================================================================
// Fused attention block via mma.sync (HMMA). fp32 accuracy via fp16 hi/lo
// split (3-term for precision-critical GEMMs; 2-term for ctx).
// 2-stage cp.async pipeline (80KB smem -> 2 CTA/SM), 128 threads / 4 warps,
// 64x64 warp tiles. qkv projections fused into one launch (z-dim).
// B=4, S=2048, D=1024.
// ============================================================================

#define TOK 8192
#define DIM 1024
#define SEQ 2048
#define BATCH 4

static const long long OUT_ELEMS = (long long)TOK * DIM;
static const long long PATTN_ELEMS = (long long)BATCH * SEQ * SEQ;
static const long long TD = (long long)TOK * DIM;

// ---------------- device scratch ----------------
__device__ __half g_xhi[TOK * DIM], g_xlo[TOK * DIM];
__device__ __half g_wThi[3 * DIM * DIM], g_wTlo[3 * DIM * DIM]; // q,k,v transposed
__device__ __half g_wpThi[DIM * DIM], g_wpTlo[DIM * DIM];
__device__ __half g_qkvhi[3 * TOK * DIM], g_qkvlo[3 * TOK * DIM];
__device__ __half g_vThi[TOK * DIM], g_vTlo[TOK * DIM];   // [B][DIM][SEQ]
__device__ __half g_phi[BATCH * SEQ * SEQ];
__device__ __half g_ctxhi[TOK * DIM], g_ctxlo[TOK * DIM];
__device__ float  g_scores_fb[BATCH * SEQ * SEQ];

// ---------------- PTX helpers ----------------
__device__ __forceinline__ uint32_t smem_u32_f(const void* p) {
    uint32_t a;
    asm("{ .reg .u64 t; cvta.to.shared.u64 t, %1; cvt.u32.u64 %0, t; }"
        : "=r"(a) : "l"(p));
    return a;
}
__device__ __forceinline__ void cp16(uint32_t dst, const void* src) {
    asm volatile("cp.async.cg.shared.global [%0], [%1], 16;" :: "r"(dst), "l"(src));
}
__device__ __forceinline__ void cp_commit() { asm volatile("cp.async.commit_group;"); }
template <int N>
__device__ __forceinline__ void cp_wait() {
    asm volatile("cp.async.wait_group %0;" :: "n"(N));
}
__device__ __forceinline__ void ldm_x4(uint32_t r[4], uint32_t addr) {
    asm volatile("ldmatrix.sync.aligned.m8n8.x4.shared.b16 {%0,%1,%2,%3}, [%4];"
                 : "=r"(r[0]), "=r"(r[1]), "=r"(r[2]), "=r"(r[3]) : "r"(addr));
}
__device__ __forceinline__ void mma16816(float c[4], const uint32_t a[4],
                                         const uint32_t b0, const uint32_t b1) {
    asm volatile(
        "mma.sync.aligned.m16n8k16.row.col.f32.f16.f16.f32 "
        "{%0,%1,%2,%3},{%4,%5,%6,%7},{%8,%9},{%0,%1,%2,%3};"
        : "+f"(c[0]), "+f"(c[1]), "+f"(c[2]), "+f"(c[3])
        : "r"(a[0]), "r"(a[1]), "r"(a[2]), "r"(a[3]), "r"(b0), "r"(b1));
}

// smem tile: 128 rows x 32 halfs, pitch 80B (64B data + 16B pad, conflict-free)
#define PITCH 80u
#define TILE_B (128u * PITCH)            // 10240 B
#define T_AH 0u
#define T_AL TILE_B
#define T_BH (2u * TILE_B)
#define T_BL (3u * TILE_B)
#define STG  (4u * TILE_B)               // 40960 B per stage
#define SMEM_DYN (2 * 4 * 10240)         // 81920 B -> 2 CTA/SM

// ============================================================================
// GEMM core: C[128,128 tile] = alpha * (Ah[+Al]) @ (Bh+Bl)^T (+bias)
// 128 threads, 4 warps, 64x64 warp tiles, BK=32, 2-stage cp.async.
// ============================================================================
template <bool ASPLIT, bool WF32, bool HASBIAS>
__device__ __forceinline__ void gemm_core(
    const __half* __restrict__ Ah, const __half* __restrict__ Al,
    const __half* __restrict__ Bh, const __half* __restrict__ Bl,
    const float* __restrict__ bias,
    float* __restrict__ Cf, __half* __restrict__ Chi, __half* __restrict__ Clo,
    int N, int K, float alpha, int row0, int col0, long long cOff)
{
    extern __shared__ char smem_raw[];
    const uint32_t base = smem_u32_f(smem_raw);
    const int tid = threadIdx.x;
    const int warp = tid >> 5, lane = tid & 31;

    // cp.async slots: 512 chunks/tile, 4 per thread
    long long aOff[4], bOff[4];
    uint32_t dOff[4];
#pragma unroll
    for (int j = 0; j < 4; j++) {
        int c = tid + j * 128;
        int r = c >> 2, q = c & 3;
        aOff[j] = (long long)(row0 + r) * K + q * 8;
        bOff[j] = (long long)(col0 + r) * K + q * 8;
        dOff[j] = (uint32_t)r * PITCH + (uint32_t)q * 16u;
    }

    const int m0 = (warp & 1) * 64, n0 = (warp >> 1) * 64;
    const uint32_t aLane = (uint32_t)(lane & 15) * PITCH + (uint32_t)(lane >> 4) * 16u;
    const uint32_t bLane = (uint32_t)((lane & 7) + ((lane >> 4) << 3)) * PITCH +
                           (uint32_t)((lane >> 3) & 1) * 16u;

    float acc[4][8][4];
#pragma unroll
    for (int i = 0; i < 4; i++)
#pragma unroll
        for (int j = 0; j < 8; j++)
#pragma unroll
            for (int e = 0; e < 4; e++) acc[i][j][e] = 0.f;

    const int nk = K >> 5;

    // prologue: stage 0
    {
        uint32_t sb = base;
#pragma unroll
        for (int j = 0; j < 4; j++) {
            cp16(sb + T_AH + dOff[j], Ah + aOff[j]);
            if (ASPLIT) cp16(sb + T_AL + dOff[j], Al + aOff[j]);
            cp16(sb + T_BH + dOff[j], Bh + bOff[j]);
            cp16(sb + T_BL + dOff[j], Bl + bOff[j]);
        }
        cp_commit();
    }

    for (int i = 0; i < nk; i++) {
        if (i + 1 < nk) {
            uint32_t sb = base + (uint32_t)((i + 1) & 1) * STG;
            long long k0 = (long long)(i + 1) * 32;
#pragma unroll
            for (int j = 0; j < 4; j++) {
                cp16(sb + T_AH + dOff[j], Ah + aOff[j] + k0);
                if (ASPLIT) cp16(sb + T_AL + dOff[j], Al + aOff[j] + k0);
                cp16(sb + T_BH + dOff[j], Bh + bOff[j] + k0);
                cp16(sb + T_BL + dOff[j], Bl + bOff[j] + k0);
            }
            cp_commit();
            cp_wait<1>();
        } else {
            cp_wait<0>();
        }
        __syncthreads();

        const uint32_t sb = base + (uint32_t)(i & 1) * STG;
#pragma unroll
        for (int ks = 0; ks < 2; ks++) {
            const uint32_t kb = (uint32_t)ks * 32u;
            uint32_t ah[4][4], al[4][4], bh[4][4], bl[4][4];
#pragma unroll
            for (int mf = 0; mf < 4; mf++) {
                uint32_t ro = (uint32_t)(m0 + mf * 16) * PITCH + kb + aLane;
                ldm_x4(ah[mf], sb + T_AH + ro);
                if (ASPLIT) ldm_x4(al[mf], sb + T_AL + ro);
            }
#pragma unroll
            for (int q = 0; q < 4; q++) {
                uint32_t ro = (uint32_t)(n0 + q * 16) * PITCH + kb + bLane;
                ldm_x4(bh[q], sb + T_BH + ro);
                ldm_x4(bl[q], sb + T_BL + ro);
            }
#pragma unroll
            for (int mf = 0; mf < 4; mf++)
#pragma unroll
                for (int nf = 0; nf < 8; nf++) {
                    const int q = nf >> 1, h = (nf & 1) * 2;
                    mma16816(acc[mf][nf], ah[mf], bh[q][h], bh[q][h + 1]);
                    if (ASPLIT) mma16816(acc[mf][nf], al[mf], bh[q][h], bh[q][h + 1]);
                    mma16816(acc[mf][nf], ah[mf], bl[q][h], bl[q][h + 1]);
                }
        }
        __syncthreads();
    }

    // ---- epilogue ----
    const int tg = lane >> 2, tl = lane & 3;
#pragma unroll
    for (int mf = 0; mf < 4; mf++) {
#pragma unroll
        for (int nf = 0; nf < 8; nf++) {
            const int col = col0 + n0 + nf * 8 + tl * 2;
            float b0 = 0.f, b1 = 0.f;
            if (HASBIAS) { b0 = __ldg(bias + col); b1 = __ldg(bias + col + 1); }
#pragma unroll
            for (int hrow = 0; hrow < 2; hrow++) {
                const int row = row0 + m0 + mf * 16 + tg + hrow * 8;
                float v0 = acc[mf][nf][hrow * 2 + 0] * alpha + b0;
                float v1 = acc[mf][nf][hrow * 2 + 1] * alpha + b1;
                const long long off = cOff + (long long)row * N + col;
                if (WF32) {
                    float2 o; o.x = v0; o.y = v1;
                    *(float2*)(Cf + off) = o;
                } else {
                    __half h0 = __float2half_rn(v0);
                    __half h1 = __float2half_rn(v1);
                    __half2 th; th.x = h0; th.y = h1;
                    __half2 tlh;
                    tlh.x = __float2half_rn(v0 - __half2float(h0));
                    tlh.y = __float2half_rn(v1 - __half2float(h1));
                    *(__half2*)(Chi + off) = th;
                    *(__half2*)(Clo + off) = tlh;
                }
            }
        }
    }
}

// generic GEMM (scores / ctx / out-proj)
template <bool ASPLIT, bool WF32, bool HASBIAS>
__global__ void __launch_bounds__(128) mma_gemm(
    const __half* __restrict__ Ah_g, const __half* __restrict__ Al_g,
    const __half* __restrict__ Bh_g, const __half* __restrict__ Bl_g,
    const float* __restrict__ bias,
    float* __restrict__ Cf, __half* __restrict__ Chi, __half* __restrict__ Clo,
    int N, int K, float alpha,
    long long sA, long long sB, long long sC)
{
    const long long zb = blockIdx.z;
    gemm_core<ASPLIT, WF32, HASBIAS>(
        Ah_g + zb * sA, ASPLIT ? (Al_g + zb * sA) : nullptr,
        Bh_g + zb * sB, Bl_g + zb * sB, bias,
        Cf, Chi, Clo, N, K, alpha,
        blockIdx.y * 128, blockIdx.x * 128, zb * sC);
}

// fused q/k/v projection: z selects weight slab, bias, and output slab
__global__ void __launch_bounds__(128) qkv_gemm(
    const __half* __restrict__ xhi, const __half* __restrict__ xlo,
    const __half* __restrict__ wThi, const __half* __restrict__ wTlo,
    const float* __restrict__ bq, const float* __restrict__ bk,
    const float* __restrict__ bv,
    __half* __restrict__ outhi, __half* __restrict__ outlo)
{
    const int z = blockIdx.z;
    const float* bias = (z == 0) ? bq : (z == 1) ? bk : bv;
    const long long wOff = (long long)z * DIM * DIM;
    gemm_core<true, false, true>(
        xhi, xlo, wThi + wOff, wTlo + wOff, bias,
        nullptr, outhi, outlo, DIM, DIM, 1.f,
        blockIdx.y * 128, blockIdx.x * 128, (long long)z * TD);
}

// ============================================================================
// helper kernels
// ============================================================================
__global__ void __launch_bounds__(256) convert_split_kernel(
    const float* __restrict__ in, __half* __restrict__ hi,
    __half* __restrict__ lo, long long n4)
{
    long long i = (long long)blockIdx.x * 256 + threadIdx.x;
    if (i >= n4) return;
    float4 v = ((const float4*)in)[i];
    __half h0 = __float2half_rn(v.x), h1 = __float2half_rn(v.y);
    __half h2 = __float2half_rn(v.z), h3 = __float2half_rn(v.w);
    __half2 a, b; a.x = h0; a.y = h1; b.x = h2; b.y = h3;
    ((__half2*)hi)[i * 2 + 0] = a;
    ((__half2*)hi)[i * 2 + 1] = b;
    __half2 c, d;
    c.x = __float2half_rn(v.x - __half2float(h0));
    c.y = __float2half_rn(v.y - __half2float(h1));
    d.x = __float2half_rn(v.z - __half2float(h2));
    d.y = __float2half_rn(v.w - __half2float(h3));
    ((__half2*)lo)[i * 2 + 0] = c;
    ((__half2*)lo)[i * 2 + 1] = d;
}

// fp32 transpose+split (weights): out[c][r] = split(in[r][c])
__global__ void __launch_bounds__(256) transpose_split_kernel(
    const float* __restrict__ in, __half* __restrict__ hi,
    __half* __restrict__ lo, int R, int C)
{
    __shared__ float t[32][33];
    const int c0 = blockIdx.x * 32, r0 = blockIdx.y * 32;
    const int tx = threadIdx.x & 31, ty = threadIdx.x >> 5;
#pragma unroll
    for (int j = 0; j < 4; j++)
        t[ty + j * 8][tx] = in[(long long)(r0 + ty + j * 8) * C + c0 + tx];
    __syncthreads();
#pragma unroll
    for (int j = 0; j < 4; j++) {
        int oc = c0 + ty + j * 8;
        float v = t[tx][ty + j * 8];
        long long o = (long long)oc * R + r0 + tx;
        __half h = __float2half_rn(v);
        hi[o] = h;
        lo[o] = __float2half_rn(v - __half2float(h));
    }
}

// fp16 hi+lo transpose (v): per batch, vT[d][t] = v[t][d]
__global__ void __launch_bounds__(256) transpose_half_kernel(
    const __half* __restrict__ hi_in, const __half* __restrict__ lo_in,
    __half* __restrict__ hi_out, __half* __restrict__ lo_out,
    int R, int C, long long sIn, long long sOut)
{
    __shared__ __half th[32][34], tl[32][34];
    const __half* hsrc = hi_in + (long long)blockIdx.z * sIn;
    const __half* lsrc = lo_in + (long long)blockIdx.z * sIn;
    const int c0 = blockIdx.x * 32, r0 = blockIdx.y * 32;
    const int tx = threadIdx.x & 31, ty = threadIdx.x >> 5;
#pragma unroll
    for (int j = 0; j < 4; j++) {
        long long src = (long long)(r0 + ty + j * 8) * C + c0 + tx;
        th[ty + j * 8][tx] = hsrc[src];
        tl[ty + j * 8][tx] = lsrc[src];
    }
    __syncthreads();
#pragma unroll
    for (int j = 0; j < 4; j++) {
        int oc = c0 + ty + j * 8;
        long long o = (long long)blockIdx.z * sOut + (long long)oc * R + r0 + tx;
        hi_out[o] = th[tx][ty + j * 8];
        lo_out[o] = tl[tx][ty + j * 8];
    }
}

// softmax rows of 2048 (fp32 in place) + fp16 p_hi output
__global__ void __launch_bounds__(256) softmax2048_kernel(
    float* __restrict__ p, __half* __restrict__ phi)
{
    const long long roff = (long long)blockIdx.x * 2048;
    float* row = p + roff;
    const int tid = threadIdx.x;

    float4 v0 = ((const float4*)row)[tid];
    float4 v1 = ((const float4*)row)[tid + 256];

    float m = fmaxf(fmaxf(fmaxf(v0.x, v0.y), fmaxf(v0.z, v0.w)),
                    fmaxf(fmaxf(v1.x, v1.y), fmaxf(v1.z, v1.w)));
    __shared__ float red[8];
#pragma unroll
    for (int o = 16; o; o >>= 1) m = fmaxf(m, __shfl_xor_sync(0xffffffffu, m, o));
    if ((tid & 31) == 0) red[tid >> 5] = m;
    __syncthreads();
    m = red[0];
#pragma unroll
    for (int i = 1; i < 8; i++) m = fmaxf(m, red[i]);
    __syncthreads();

    v0.x = expf(v0.x - m); v0.y = expf(v0.y - m);
    v0.z = expf(v0.z - m); v0.w = expf(v0.w - m);
    v1.x = expf(v1.x - m); v1.y = expf(v1.y - m);
    v1.z = expf(v1.z - m); v1.w = expf(v1.w - m);

    float s = (v0.x + v0.y) + (v0.z + v0.w) + (v1.x + v1.y) + (v1.z + v1.w);
#pragma unroll
    for (int o = 16; o; o >>= 1) s += __shfl_xor_sync(0xffffffffu, s, o);
    if ((tid & 31) == 0) red[tid >> 5] = s;
    __syncthreads();
    s = ((red[0] + red[1]) + (red[2] + red[3])) +
        ((red[4] + red[5]) + (red[6] + red[7]));
    float inv = 1.0f / s;

    v0.x *= inv; v0.y *= inv; v0.z *= inv; v0.w *= inv;
    v1.x *= inv; v1.y *= inv; v1.z *= inv; v1.w *= inv;

    ((float4*)row)[tid] = v0;
    ((float4*)row)[tid + 256] = v1;

    const float vv[8] = {v0.x, v0.y, v0.z, v0.w, v1.x, v1.y, v1.z, v1.w};
    const long long off[2] = {roff + (long long)tid * 4,
                              roff + (long long)(tid + 256) * 4};
#pragma unroll
    for (int hseg = 0; hseg < 2; hseg++) {
#pragma unroll
        for (int g = 0; g < 2; g++) {
            __half2 th;
            th.x = __float2half_rn(vv[hseg * 4 + g * 2]);
            th.y = __float2half_rn(vv[hseg * 4 + g * 2 + 1]);
            *(__half2*)(phi + off[hseg] + g * 2) = th;
        }
    }
}

// ============================================================================
// host launcher
// ============================================================================
extern "C" void kernel_launch(void* const* d_in, const int* in_sizes, int n_in,
                              void* d_out, int out_size)
{
    const float* x  = (const float*)d_in[0];
    const float* wq = (const float*)d_in[1];
    const float* bq = (const float*)d_in[2];
    const float* wk = (const float*)d_in[3];
    const float* bk = (const float*)d_in[4];
    const float* wv = (const float*)d_in[5];
    const float* bv = (const float*)d_in[6];
    const float* wp = (const float*)d_in[7];
    const float* bp = (const float*)d_in[8];
    float* out = (float*)d_out;

#define SYM(p, s) void* p##_; cudaGetSymbolAddress(&p##_, s);
    SYM(xhi, g_xhi) SYM(xlo, g_xlo)
    SYM(wth, g_wThi) SYM(wtl, g_wTlo)
    SYM(wph, g_wpThi) SYM(wpl, g_wpTlo)
    SYM(qkvh, g_qkvhi) SYM(qkvl, g_qkvlo)
    SYM(vth, g_vThi) SYM(vtl, g_vTlo)
    SYM(phi, g_phi)
    SYM(cxh, g_ctxhi) SYM(cxl, g_ctxlo)
    SYM(sfb, g_scores_fb)
#undef SYM
#define HF(p) ((__half*)p##_)

    float* pattn = (out_size >= (long long)(OUT_ELEMS + PATTN_ELEMS))
                       ? (out + OUT_ELEMS) : (float*)sfb_;

    cudaFuncSetAttribute(qkv_gemm, cudaFuncAttributeMaxDynamicSharedMemorySize, SMEM_DYN);
    cudaFuncSetAttribute(mma_gemm<true,  true,  false>, cudaFuncAttributeMaxDynamicSharedMemorySize, SMEM_DYN);
    cudaFuncSetAttribute(mma_gemm<false, false, false>, cudaFuncAttributeMaxDynamicSharedMemorySize, SMEM_DYN);
    cudaFuncSetAttribute(mma_gemm<true,  true,  true >, cudaFuncAttributeMaxDynamicSharedMemorySize, SMEM_DYN);

    // 1) split x
    convert_split_kernel<<<(TOK * DIM / 4 + 255) / 256, 256>>>(
        x, HF(xhi), HF(xlo), TOK * DIM / 4);

    // 2) transpose + split weights: wT[n][k] = w[k][n]
    dim3 gW(DIM / 32, DIM / 32, 1);
    transpose_split_kernel<<<gW, 256>>>(wq, HF(wth) + 0 * DIM * DIM, HF(wtl) + 0 * DIM * DIM, DIM, DIM);
    transpose_split_kernel<<<gW, 256>>>(wk, HF(wth) + 1 * DIM * DIM, HF(wtl) + 1 * DIM * DIM, DIM, DIM);
    transpose_split_kernel<<<gW, 256>>>(wv, HF(wth) + 2 * DIM * DIM, HF(wtl) + 2 * DIM * DIM, DIM, DIM);
    transpose_split_kernel<<<gW, 256>>>(wp, HF(wph), HF(wpl), DIM, DIM);

    // 3) fused q,k,v projections (3-term) -> fp16 splits
    dim3 gQKV(DIM / 128, TOK / 128, 3);
    qkv_gemm<<<gQKV, 128, SMEM_DYN>>>(
        HF(xhi), HF(xlo), HF(wth), HF(wtl), bq, bk, bv, HF(qkvh), HF(qkvl));

    const __half* qhi = HF(qkvh) + 0 * TD; const __half* qlo = HF(qkvl) + 0 * TD;
    const __half* khi = HF(qkvh) + 1 * TD; const __half* klo = HF(qkvl) + 1 * TD;
    const __half* vhi = HF(qkvh) + 2 * TD; const __half* vlo = HF(qkvl) + 2 * TD;

    // 4) transpose v splits per batch -> vT[b][d][t]
    dim3 gVT(DIM / 32, SEQ / 32, BATCH);
    transpose_half_kernel<<<gVT, 256>>>(vhi, vlo, HF(vth), HF(vtl),
                                        SEQ, DIM,
                                        (long long)SEQ * DIM, (long long)DIM * SEQ);

    // 5) scores = 32 * q @ k^T (3-term) -> fp32 p_attn region
    dim3 gSc(SEQ / 128, SEQ / 128, BATCH);
    mma_gemm<true, true, false><<<gSc, 128, SMEM_DYN>>>(
        qhi, qlo, khi, klo, nullptr, pattn, nullptr, nullptr,
        SEQ, DIM, 32.f,
        (long long)SEQ * DIM, (long long)SEQ * DIM, (long long)SEQ * SEQ);

    // 6) softmax in place + fp16 p_hi
    softmax2048_kernel<<<TOK, 256>>>(pattn, HF(phi));

    // 7) ctx = p @ v (2-term: p_hi*(v_hi+v_lo)) -> fp16 split
    dim3 gCtx(DIM / 128, SEQ / 128, BATCH);
    mma_gemm<false, false, false><<<gCtx, 128, SMEM_DYN>>>(
        HF(phi), nullptr, HF(vth), HF(vtl), nullptr, nullptr, HF(cxh), HF(cxl),
        DIM, SEQ, 1.f,
        (long long)SEQ * SEQ, (long long)DIM * SEQ, (long long)SEQ * DIM);

    // 8) out = ctx @ wp + bp (3-term)
    dim3 gOut(DIM / 128, TOK / 128, 1);
    mma_gemm<true, true, true><<<gOut, 128, SMEM_DYN>>>(
        HF(cxh), HF(cxl), HF(wph), HF(wpl), bp, out, nullptr, nullptr,
        DIM, DIM, 1.f, 0, 0, 0);
}

// round 6
// speedup vs baseline: 1.4065x; 1.1392x over previous
#include <cuda_runtime.h>
#include <cuda_fp16.h>
#include <cstdint>

// ============================================================================
// Fused attention block via mma.sync (HMMA). fp16 hi/lo split arithmetic:
//   - 3-term (Markidis) for q/k projections and scores (exp() amplifies)
//   - 2-term for v/out projections, 1-term for ctx (forgiving path)
// 2-stage cp.async, ONE __syncthreads per K-iter, 128 thr / 4 warps,
// 64x64 warp tiles, 2 CTA/SM. B=4, S=2048, D=1024.
// ============================================================================

#define TOK 8192
#define DIM 1024
#define SEQ 2048
#define BATCH 4

static const long long OUT_ELEMS = (long long)TOK * DIM;
static const long long PATTN_ELEMS = (long long)BATCH * SEQ * SEQ;
static const long long TD = (long long)TOK * DIM;

// ---------------- device scratch ----------------
__device__ __half g_xhi[TOK * DIM], g_xlo[TOK * DIM];
__device__ __half g_wThi[3 * DIM * DIM], g_wTlo[3 * DIM * DIM]; // q,k,v ^T
__device__ __half g_wpThi[DIM * DIM], g_wpTlo[DIM * DIM];
__device__ __half g_qkvhi[3 * TOK * DIM];
__device__ __half g_qkvlo[2 * TOK * DIM];                 // lo only for q,k
__device__ __half g_vThi[TOK * DIM];                      // [B][DIM][SEQ]
__device__ __half g_phi[BATCH * SEQ * SEQ];
__device__ __half g_ctxhi[TOK * DIM];
__device__ float  g_scores_fb[BATCH * SEQ * SEQ];

// ---------------- PTX helpers ----------------
__device__ __forceinline__ uint32_t smem_u32_f(const void* p) {
    uint32_t a;
    asm("{ .reg .u64 t; cvta.to.shared.u64 t, %1; cvt.u32.u64 %0, t; }"
        : "=r"(a) : "l"(p));
    return a;
}
__device__ __forceinline__ void cp16(uint32_t dst, const void* src) {
    asm volatile("cp.async.cg.shared.global [%0], [%1], 16;" :: "r"(dst), "l"(src));
}
__device__ __forceinline__ void cp_commit() { asm volatile("cp.async.commit_group;"); }
template <int N>
__device__ __forceinline__ void cp_wait() {
    asm volatile("cp.async.wait_group %0;" :: "n"(N));
}
__device__ __forceinline__ void ldm_x4(uint32_t r[4], uint32_t addr) {
    asm volatile("ldmatrix.sync.aligned.m8n8.x4.shared.b16 {%0,%1,%2,%3}, [%4];"
                 : "=r"(r[0]), "=r"(r[1]), "=r"(r[2]), "=r"(r[3]) : "r"(addr));
}
__device__ __forceinline__ void mma16816(float c[4], const uint32_t a[4],
                                         const uint32_t b0, const uint32_t b1) {
    asm volatile(
        "mma.sync.aligned.m16n8k16.row.col.f32.f16.f16.f32 "
        "{%0,%1,%2,%3},{%4,%5,%6,%7},{%8,%9},{%0,%1,%2,%3};"
        : "+f"(c[0]), "+f"(c[1]), "+f"(c[2]), "+f"(c[3])
        : "r"(a[0]), "r"(a[1]), "r"(a[2]), "r"(a[3]), "r"(b0), "r"(b1));
}

// smem tile: 128 rows x 32 halfs, pitch 80B (conflict-free for ldmatrix)
#define PITCH 80u
#define TILE_B (128u * PITCH)            // 10240 B
#define SMEM_DYN (2 * 4 * 10240)         // 81920 B (max variant) -> 2 CTA/SM

// ============================================================================
// GEMM core. Terms: ah*bh [+ al*bh if ASPLIT] [+ ah*bl if BSPLIT].
// Output: fp32 (WF32) or fp16 hi [+ lo if WLO].
// ============================================================================
template <bool ASPLIT, bool BSPLIT, bool WF32, bool HASBIAS, bool WLO>
__device__ __forceinline__ void gemm_core(
    const __half* __restrict__ Ah, const __half* __restrict__ Al,
    const __half* __restrict__ Bh, const __half* __restrict__ Bl,
    const float* __restrict__ bias,
    float* __restrict__ Cf, __half* __restrict__ Chi, __half* __restrict__ Clo,
    int N, int K, float alpha, int row0, int col0, long long cOff)
{
    // compact per-variant stage layout
    constexpr uint32_t OF_AH = 0u;
    constexpr uint32_t OF_BH = TILE_B;
    constexpr uint32_t OF_AL = 2u * TILE_B;                      // if ASPLIT
    constexpr uint32_t OF_BL = (ASPLIT ? 3u : 2u) * TILE_B;      // if BSPLIT
    constexpr uint32_t STG_SZ = (2u + (ASPLIT ? 1u : 0u) + (BSPLIT ? 1u : 0u)) * TILE_B;

    extern __shared__ char smem_raw[];
    const uint32_t base = smem_u32_f(smem_raw);
    const int tid = threadIdx.x;
    const int warp = tid >> 5, lane = tid & 31;

    long long aOff[4], bOff[4];
    uint32_t dOff[4];
#pragma unroll
    for (int j = 0; j < 4; j++) {
        int c = tid + j * 128;
        int r = c >> 2, q = c & 3;
        aOff[j] = (long long)(row0 + r) * K + q * 8;
        bOff[j] = (long long)(col0 + r) * K + q * 8;
        dOff[j] = (uint32_t)r * PITCH + (uint32_t)q * 16u;
    }

    const int m0 = (warp & 1) * 64, n0 = (warp >> 1) * 64;
    const uint32_t aLane = (uint32_t)(lane & 15) * PITCH + (uint32_t)(lane >> 4) * 16u;
    const uint32_t bLane = (uint32_t)((lane & 7) + ((lane >> 4) << 3)) * PITCH +
                           (uint32_t)((lane >> 3) & 1) * 16u;

    float acc[4][8][4];
#pragma unroll
    for (int i = 0; i < 4; i++)
#pragma unroll
        for (int j = 0; j < 8; j++)
#pragma unroll
            for (int e = 0; e < 4; e++) acc[i][j][e] = 0.f;

    const int nk = K >> 5;

    // prologue: stage 0
    {
        uint32_t sb = base;
#pragma unroll
        for (int j = 0; j < 4; j++) {
            cp16(sb + OF_AH + dOff[j], Ah + aOff[j]);
            if (ASPLIT) cp16(sb + OF_AL + dOff[j], Al + aOff[j]);
            cp16(sb + OF_BH + dOff[j], Bh + bOff[j]);
            if (BSPLIT) cp16(sb + OF_BL + dOff[j], Bl + bOff[j]);
        }
        cp_commit();
    }

    for (int i = 0; i < nk; i++) {
        cp_wait<0>();        // stage i resident
        __syncthreads();     // all warps done with compute(i-1) -> buffer free

        if (i + 1 < nk) {    // prefetch stage i+1 into the freed buffer
            uint32_t sb = base + (uint32_t)((i + 1) & 1) * STG_SZ;
            long long k0 = (long long)(i + 1) * 32;
#pragma unroll
            for (int j = 0; j < 4; j++) {
                cp16(sb + OF_AH + dOff[j], Ah + aOff[j] + k0);
                if (ASPLIT) cp16(sb + OF_AL + dOff[j], Al + aOff[j] + k0);
                cp16(sb + OF_BH + dOff[j], Bh + bOff[j] + k0);
                if (BSPLIT) cp16(sb + OF_BL + dOff[j], Bl + bOff[j] + k0);
            }
            cp_commit();
        }

        const uint32_t sb = base + (uint32_t)(i & 1) * STG_SZ;
#pragma unroll
        for (int ks = 0; ks < 2; ks++) {
            const uint32_t kb = (uint32_t)ks * 32u;
            uint32_t ah[4][4], al[4][4], bh[4][4], bl[4][4];
#pragma unroll
            for (int mf = 0; mf < 4; mf++) {
                uint32_t ro = (uint32_t)(m0 + mf * 16) * PITCH + kb + aLane;
                ldm_x4(ah[mf], sb + OF_AH + ro);
                if (ASPLIT) ldm_x4(al[mf], sb + OF_AL + ro);
            }
#pragma unroll
            for (int q = 0; q < 4; q++) {
                uint32_t ro = (uint32_t)(n0 + q * 16) * PITCH + kb + bLane;
                ldm_x4(bh[q], sb + OF_BH + ro);
                if (BSPLIT) ldm_x4(bl[q], sb + OF_BL + ro);
            }
#pragma unroll
            for (int mf = 0; mf < 4; mf++)
#pragma unroll
                for (int nf = 0; nf < 8; nf++) {
                    const int q = nf >> 1, h = (nf & 1) * 2;
                    mma16816(acc[mf][nf], ah[mf], bh[q][h], bh[q][h + 1]);
                    if (ASPLIT) mma16816(acc[mf][nf], al[mf], bh[q][h], bh[q][h + 1]);
                    if (BSPLIT) mma16816(acc[mf][nf], ah[mf], bl[q][h], bl[q][h + 1]);
                }
        }
    }

    // ---- epilogue (reads regs only; no smem reuse -> no sync needed) ----
    const int tg = lane >> 2, tl = lane & 3;
#pragma unroll
    for (int mf = 0; mf < 4; mf++) {
#pragma unroll
        for (int nf = 0; nf < 8; nf++) {
            const int col = col0 + n0 + nf * 8 + tl * 2;
            float b0 = 0.f, b1 = 0.f;
            if (HASBIAS) { b0 = __ldg(bias + col); b1 = __ldg(bias + col + 1); }
#pragma unroll
            for (int hrow = 0; hrow < 2; hrow++) {
                const int row = row0 + m0 + mf * 16 + tg + hrow * 8;
                float v0 = acc[mf][nf][hrow * 2 + 0] * alpha + b0;
                float v1 = acc[mf][nf][hrow * 2 + 1] * alpha + b1;
                const long long off = cOff + (long long)row * N + col;
                if (WF32) {
                    float2 o; o.x = v0; o.y = v1;
                    *(float2*)(Cf + off) = o;
                } else {
                    __half h0 = __float2half_rn(v0);
                    __half h1 = __float2half_rn(v1);
                    __half2 th; th.x = h0; th.y = h1;
                    *(__half2*)(Chi + off) = th;
                    if (WLO) {
                        __half2 tlh;
                        tlh.x = __float2half_rn(v0 - __half2float(h0));
                        tlh.y = __float2half_rn(v1 - __half2float(h1));
                        *(__half2*)(Clo + off) = tlh;
                    }
                }
            }
        }
    }
}

// generic GEMM (scores / ctx / out-proj)
template <bool ASPLIT, bool BSPLIT, bool WF32, bool HASBIAS, bool WLO>
__global__ void __launch_bounds__(128) mma_gemm(
    const __half* __restrict__ Ah_g, const __half* __restrict__ Al_g,
    const __half* __restrict__ Bh_g, const __half* __restrict__ Bl_g,
    const float* __restrict__ bias,
    float* __restrict__ Cf, __half* __restrict__ Chi, __half* __restrict__ Clo,
    int N, int K, float alpha,
    long long sA, long long sB, long long sC)
{
    const long long zb = blockIdx.z;
    gemm_core<ASPLIT, BSPLIT, WF32, HASBIAS, WLO>(
        Ah_g + zb * sA, ASPLIT ? (Al_g + zb * sA) : nullptr,
        Bh_g + zb * sB, BSPLIT ? (Bl_g + zb * sB) : nullptr, bias,
        Cf, Chi, Clo, N, K, alpha,
        blockIdx.y * 128, blockIdx.x * 128, zb * sC);
}

// fused q/k/v projection: z in {0:q, 1:k} 3-term hi+lo; {2:v} 2-term hi-only
__global__ void __launch_bounds__(128) qkv_gemm(
    const __half* __restrict__ xhi, const __half* __restrict__ xlo,
    const __half* __restrict__ wThi, const __half* __restrict__ wTlo,
    const float* __restrict__ bq, const float* __restrict__ bk,
    const float* __restrict__ bv,
    __half* __restrict__ outhi, __half* __restrict__ outlo)
{
    const int z = blockIdx.z;
    const long long wOff = (long long)z * DIM * DIM;
    const int r0 = blockIdx.y * 128, c0 = blockIdx.x * 128;
    if (z == 2) {
        gemm_core<false, true, false, true, false>(
            xhi, nullptr, wThi + wOff, wTlo + wOff, bv,
            nullptr, outhi, nullptr, DIM, DIM, 1.f, r0, c0, 2 * TD);
    } else {
        const float* bias = (z == 0) ? bq : bk;
        gemm_core<true, true, false, true, true>(
            xhi, xlo, wThi + wOff, wTlo + wOff, bias,
            nullptr, outhi, outlo, DIM, DIM, 1.f, r0, c0, (long long)z * TD);
    }
}

// ============================================================================
// helper kernels
// ============================================================================
__global__ void __launch_bounds__(256) convert_split_kernel(
    const float* __restrict__ in, __half* __restrict__ hi,
    __half* __restrict__ lo, long long n4)
{
    long long i = (long long)blockIdx.x * 256 + threadIdx.x;
    if (i >= n4) return;
    float4 v = ((const float4*)in)[i];
    __half h0 = __float2half_rn(v.x), h1 = __float2half_rn(v.y);
    __half h2 = __float2half_rn(v.z), h3 = __float2half_rn(v.w);
    __half2 a, b; a.x = h0; a.y = h1; b.x = h2; b.y = h3;
    ((__half2*)hi)[i * 2 + 0] = a;
    ((__half2*)hi)[i * 2 + 1] = b;
    __half2 c, d;
    c.x = __float2half_rn(v.x - __half2float(h0));
    c.y = __float2half_rn(v.y - __half2float(h1));
    d.x = __float2half_rn(v.z - __half2float(h2));
    d.y = __float2half_rn(v.w - __half2float(h3));
    ((__half2*)lo)[i * 2 + 0] = c;
    ((__half2*)lo)[i * 2 + 1] = d;
}

// fp32 transpose+split (weights)
__global__ void __launch_bounds__(256) transpose_split_kernel(
    const float* __restrict__ in, __half* __restrict__ hi,
    __half* __restrict__ lo, int R, int C)
{
    __shared__ float t[32][33];
    const int c0 = blockIdx.x * 32, r0 = blockIdx.y * 32;
    const int tx = threadIdx.x & 31, ty = threadIdx.x >> 5;
#pragma unroll
    for (int j = 0; j < 4; j++)
        t[ty + j * 8][tx] = in[(long long)(r0 + ty + j * 8) * C + c0 + tx];
    __syncthreads();
#pragma unroll
    for (int j = 0; j < 4; j++) {
        int oc = c0 + ty + j * 8;
        float v = t[tx][ty + j * 8];
        long long o = (long long)oc * R + r0 + tx;
        __half h = __float2half_rn(v);
        hi[o] = h;
        lo[o] = __float2half_rn(v - __half2float(h));
    }
}

// fp16 transpose (v hi only): per batch, vT[d][t] = v[t][d]
__global__ void __launch_bounds__(256) transpose_half_kernel(
    const __half* __restrict__ in, __half* __restrict__ outp,
    int R, int C, long long sIn, long long sOut)
{
    __shared__ __half t[32][34];
    const __half* src = in + (long long)blockIdx.z * sIn;
    const int c0 = blockIdx.x * 32, r0 = blockIdx.y * 32;
    const int tx = threadIdx.x & 31, ty = threadIdx.x >> 5;
#pragma unroll
    for (int j = 0; j < 4; j++)
        t[ty + j * 8][tx] = src[(long long)(r0 + ty + j * 8) * C + c0 + tx];
    __syncthreads();
#pragma unroll
    for (int j = 0; j < 4; j++) {
        int oc = c0 + ty + j * 8;
        long long o = (long long)blockIdx.z * sOut + (long long)oc * R + r0 + tx;
        outp[o] = t[tx][ty + j * 8];
    }
}

// softmax rows of 2048 (fp32 in place) + fp16 p_hi output
__global__ void __launch_bounds__(256) softmax2048_kernel(
    float* __restrict__ p, __half* __restrict__ phi)
{
    const long long roff = (long long)blockIdx.x * 2048;
    float* row = p + roff;
    const int tid = threadIdx.x;

    float4 v0 = ((const float4*)row)[tid];
    float4 v1 = ((const float4*)row)[tid + 256];

    float m = fmaxf(fmaxf(fmaxf(v0.x, v0.y), fmaxf(v0.z, v0.w)),
                    fmaxf(fmaxf(v1.x, v1.y), fmaxf(v1.z, v1.w)));
    __shared__ float red[8];
#pragma unroll
    for (int o = 16; o; o >>= 1) m = fmaxf(m, __shfl_xor_sync(0xffffffffu, m, o));
    if ((tid & 31) == 0) red[tid >> 5] = m;
    __syncthreads();
    m = red[0];
#pragma unroll
    for (int i = 1; i < 8; i++) m = fmaxf(m, red[i]);
    __syncthreads();

    v0.x = expf(v0.x - m); v0.y = expf(v0.y - m);
    v0.z = expf(v0.z - m); v0.w = expf(v0.w - m);
    v1.x = expf(v1.x - m); v1.y = expf(v1.y - m);
    v1.z = expf(v1.z - m); v1.w = expf(v1.w - m);

    float s = (v0.x + v0.y) + (v0.z + v0.w) + (v1.x + v1.y) + (v1.z + v1.w);
#pragma unroll
    for (int o = 16; o; o >>= 1) s += __shfl_xor_sync(0xffffffffu, s, o);
    if ((tid & 31) == 0) red[tid >> 5] = s;
    __syncthreads();
    s = ((red[0] + red[1]) + (red[2] + red[3])) +
        ((red[4] + red[5]) + (red[6] + red[7]));
    float inv = 1.0f / s;

    v0.x *= inv; v0.y *= inv; v0.z *= inv; v0.w *= inv;
    v1.x *= inv; v1.y *= inv; v1.z *= inv; v1.w *= inv;

    ((float4*)row)[tid] = v0;
    ((float4*)row)[tid + 256] = v1;

    const float vv[8] = {v0.x, v0.y, v0.z, v0.w, v1.x, v1.y, v1.z, v1.w};
    const long long off[2] = {roff + (long long)tid * 4,
                              roff + (long long)(tid + 256) * 4};
#pragma unroll
    for (int hseg = 0; hseg < 2; hseg++) {
#pragma unroll
        for (int g = 0; g < 2; g++) {
            __half2 th;
            th.x = __float2half_rn(vv[hseg * 4 + g * 2]);
            th.y = __float2half_rn(vv[hseg * 4 + g * 2 + 1]);
            *(__half2*)(phi + off[hseg] + g * 2) = th;
        }
    }
}

// ============================================================================
// host launcher
// ============================================================================
extern "C" void kernel_launch(void* const* d_in, const int* in_sizes, int n_in,
                              void* d_out, int out_size)
{
    const float* x  = (const float*)d_in[0];
    const float* wq = (const float*)d_in[1];
    const float* bq = (const float*)d_in[2];
    const float* wk = (const float*)d_in[3];
    const float* bk = (const float*)d_in[4];
    const float* wv = (const float*)d_in[5];
    const float* bv = (const float*)d_in[6];
    const float* wp = (const float*)d_in[7];
    const float* bp = (const float*)d_in[8];
    float* out = (float*)d_out;

#define SYM(p, s) void* p##_; cudaGetSymbolAddress(&p##_, s);
    SYM(xhi, g_xhi) SYM(xlo, g_xlo)
    SYM(wth, g_wThi) SYM(wtl, g_wTlo)
    SYM(wph, g_wpThi) SYM(wpl, g_wpTlo)
    SYM(qkvh, g_qkvhi) SYM(qkvl, g_qkvlo)
    SYM(vth, g_vThi)
    SYM(phi, g_phi)
    SYM(cxh, g_ctxhi)
    SYM(sfb, g_scores_fb)
#undef SYM
#define HF(p) ((__half*)p##_)

    float* pattn = (out_size >= (long long)(OUT_ELEMS + PATTN_ELEMS))
                       ? (out + OUT_ELEMS) : (float*)sfb_;

    cudaFuncSetAttribute(qkv_gemm, cudaFuncAttributeMaxDynamicSharedMemorySize, SMEM_DYN);
    cudaFuncSetAttribute(mma_gemm<true,  true,  true,  false, false>, cudaFuncAttributeMaxDynamicSharedMemorySize, SMEM_DYN);
    cudaFuncSetAttribute(mma_gemm<false, false, false, false, false>, cudaFuncAttributeMaxDynamicSharedMemorySize, SMEM_DYN);
    cudaFuncSetAttribute(mma_gemm<false, true,  true,  true,  false>, cudaFuncAttributeMaxDynamicSharedMemorySize, SMEM_DYN);

    // 1) split x
    convert_split_kernel<<<(TOK * DIM / 4 + 255) / 256, 256>>>(
        x, HF(xhi), HF(xlo), TOK * DIM / 4);

    // 2) transpose + split weights
    dim3 gW(DIM / 32, DIM / 32, 1);
    transpose_split_kernel<<<gW, 256>>>(wq, HF(wth) + 0 * DIM * DIM, HF(wtl) + 0 * DIM * DIM, DIM, DIM);
    transpose_split_kernel<<<gW, 256>>>(wk, HF(wth) + 1 * DIM * DIM, HF(wtl) + 1 * DIM * DIM, DIM, DIM);
    transpose_split_kernel<<<gW, 256>>>(wv, HF(wth) + 2 * DIM * DIM, HF(wtl) + 2 * DIM * DIM, DIM, DIM);
    transpose_split_kernel<<<gW, 256>>>(wp, HF(wph), HF(wpl), DIM, DIM);

    // 3) fused q,k,v projections
    dim3 gQKV(DIM / 128, TOK / 128, 3);
    qkv_gemm<<<gQKV, 128, SMEM_DYN>>>(
        HF(xhi), HF(xlo), HF(wth), HF(wtl), bq, bk, bv, HF(qkvh), HF(qkvl));

    const __half* qhi = HF(qkvh) + 0 * TD; const __half* qlo = HF(qkvl) + 0 * TD;
    const __half* khi = HF(qkvh) + 1 * TD; const __half* klo = HF(qkvl) + 1 * TD;
    const __half* vhi = HF(qkvh) + 2 * TD;

    // 4) transpose v (hi only) per batch -> vT[b][d][t]
    dim3 gVT(DIM / 32, SEQ / 32, BATCH);
    transpose_half_kernel<<<gVT, 256>>>(vhi, HF(vth), SEQ, DIM,
                                        (long long)SEQ * DIM, (long long)DIM * SEQ);

    // 5) scores = 32 * q @ k^T (3-term) -> fp32 p_attn region
    dim3 gSc(SEQ / 128, SEQ / 128, BATCH);
    mma_gemm<true, true, true, false, false><<<gSc, 128, SMEM_DYN>>>(
        qhi, qlo, khi, klo, nullptr, pattn, nullptr, nullptr,
        SEQ, DIM, 32.f,
        (long long)SEQ * DIM, (long long)SEQ * DIM, (long long)SEQ * SEQ);

    // 6) softmax in place + fp16 p_hi
    softmax2048_kernel<<<TOK, 256>>>(pattn, HF(phi));

    // 7) ctx = p_hi @ v_hi (1-term) -> fp16 hi
    dim3 gCtx(DIM / 128, SEQ / 128, BATCH);
    mma_gemm<false, false, false, false, false><<<gCtx, 128, SMEM_DYN>>>(
        HF(phi), nullptr, HF(vth), nullptr, nullptr, nullptr, HF(cxh), nullptr,
        DIM, SEQ, 1.f,
        (long long)SEQ * SEQ, (long long)DIM * SEQ, (long long)SEQ * DIM);

    // 8) out = ctx_hi @ (wp_hi + wp_lo) + bp (2-term)
    dim3 gOut(DIM / 128, TOK / 128, 1);
    mma_gemm<false, true, true, true, false><<<gOut, 128, SMEM_DYN>>>(
        HF(cxh), nullptr, HF(wph), HF(wpl), bp, out, nullptr, nullptr,
        DIM, DIM, 1.f, 0, 0, 0);
}

// round 7
// speedup vs baseline: 1.4286x; 1.0157x over previous
#include <cuda_runtime.h>
#include <cuda_fp16.h>
#include <cstdint>

// ============================================================================
// Fused attention block via mma.sync (HMMA). fp16 hi/lo split arithmetic:
//   - 3-term (Markidis) for q/k projections and scores (exp() amplifies)
//   - 2-term for v/out projections, 1-term for ctx (forgiving path)
// Persistent-CTA tile scheduler (grid = 2*SMs, grid-stride over tiles) to
// eliminate wave quantization. 2-stage cp.async, one __syncthreads per
// K-iter, 128 thr / 4 warps, 64x64 warp tiles, 2 CTA/SM.
// B=4, S=2048, D=1024.
// ============================================================================

#define TOK 8192
#define DIM 1024
#define SEQ 2048
#define BATCH 4

static const long long OUT_ELEMS = (long long)TOK * DIM;
static const long long PATTN_ELEMS = (long long)BATCH * SEQ * SEQ;
static const long long TD = (long long)TOK * DIM;

// ---------------- device scratch ----------------
__device__ __half g_xhi[TOK * DIM], g_xlo[TOK * DIM];
__device__ __half g_wThi[3 * DIM * DIM], g_wTlo[3 * DIM * DIM]; // q,k,v ^T
__device__ __half g_wpThi[DIM * DIM], g_wpTlo[DIM * DIM];
__device__ __half g_qkvhi[3 * TOK * DIM];
__device__ __half g_qkvlo[2 * TOK * DIM];                 // lo only for q,k
__device__ __half g_vThi[TOK * DIM];                      // [B][DIM][SEQ]
__device__ __half g_phi[BATCH * SEQ * SEQ];
__device__ __half g_ctxhi[TOK * DIM];
__device__ float  g_scores_fb[BATCH * SEQ * SEQ];

// ---------------- PTX helpers ----------------
__device__ __forceinline__ uint32_t smem_u32_f(const void* p) {
    uint32_t a;
    asm("{ .reg .u64 t; cvta.to.shared.u64 t, %1; cvt.u32.u64 %0, t; }"
        : "=r"(a) : "l"(p));
    return a;
}
__device__ __forceinline__ void cp16(uint32_t dst, const void* src) {
    asm volatile("cp.async.cg.shared.global [%0], [%1], 16;" :: "r"(dst), "l"(src));
}
__device__ __forceinline__ void cp_commit() { asm volatile("cp.async.commit_group;"); }
template <int N>
__device__ __forceinline__ void cp_wait() {
    asm volatile("cp.async.wait_group %0;" :: "n"(N));
}
__device__ __forceinline__ void ldm_x4(uint32_t r[4], uint32_t addr) {
    asm volatile("ldmatrix.sync.aligned.m8n8.x4.shared.b16 {%0,%1,%2,%3}, [%4];"
                 : "=r"(r[0]), "=r"(r[1]), "=r"(r[2]), "=r"(r[3]) : "r"(addr));
}
__device__ __forceinline__ void mma16816(float c[4], const uint32_t a[4],
                                         const uint32_t b0, const uint32_t b1) {
    asm volatile(
        "mma.sync.aligned.m16n8k16.row.col.f32.f16.f16.f32 "
        "{%0,%1,%2,%3},{%4,%5,%6,%7},{%8,%9},{%0,%1,%2,%3};"
        : "+f"(c[0]), "+f"(c[1]), "+f"(c[2]), "+f"(c[3])
        : "r"(a[0]), "r"(a[1]), "r"(a[2]), "r"(a[3]), "r"(b0), "r"(b1));
}

// smem tile: 128 rows x 32 halfs, pitch 80B (conflict-free for ldmatrix)
#define PITCH 80u
#define TILE_B (128u * PITCH)            // 10240 B
#define SMEM_DYN (2 * 4 * 10240)         // 81920 B (max variant) -> 2 CTA/SM

// ============================================================================
// GEMM core for one 128x128 output tile.
// Terms: ah*bh [+ al*bh if ASPLIT] [+ ah*bl if BSPLIT].
// ============================================================================
template <bool ASPLIT, bool BSPLIT, bool WF32, bool HASBIAS, bool WLO>
__device__ __forceinline__ void gemm_core(
    const __half* __restrict__ Ah, const __half* __restrict__ Al,
    const __half* __restrict__ Bh, const __half* __restrict__ Bl,
    const float* __restrict__ bias,
    float* __restrict__ Cf, __half* __restrict__ Chi, __half* __restrict__ Clo,
    int N, int K, float alpha, int row0, int col0, long long cOff)
{
    constexpr uint32_t OF_AH = 0u;
    constexpr uint32_t OF_BH = TILE_B;
    constexpr uint32_t OF_AL = 2u * TILE_B;
    constexpr uint32_t OF_BL = (ASPLIT ? 3u : 2u) * TILE_B;
    constexpr uint32_t STG_SZ = (2u + (ASPLIT ? 1u : 0u) + (BSPLIT ? 1u : 0u)) * TILE_B;

    extern __shared__ char smem_raw[];
    const uint32_t base = smem_u32_f(smem_raw);
    const int tid = threadIdx.x;
    const int warp = tid >> 5, lane = tid & 31;

    long long aOff[4], bOff[4];
    uint32_t dOff[4];
#pragma unroll
    for (int j = 0; j < 4; j++) {
        int c = tid + j * 128;
        int r = c >> 2, q = c & 3;
        aOff[j] = (long long)(row0 + r) * K + q * 8;
        bOff[j] = (long long)(col0 + r) * K + q * 8;
        dOff[j] = (uint32_t)r * PITCH + (uint32_t)q * 16u;
    }

    const int m0 = (warp & 1) * 64, n0 = (warp >> 1) * 64;
    const uint32_t aLane = (uint32_t)(lane & 15) * PITCH + (uint32_t)(lane >> 4) * 16u;
    const uint32_t bLane = (uint32_t)((lane & 7) + ((lane >> 4) << 3)) * PITCH +
                           (uint32_t)((lane >> 3) & 1) * 16u;

    float acc[4][8][4];
#pragma unroll
    for (int i = 0; i < 4; i++)
#pragma unroll
        for (int j = 0; j < 8; j++)
#pragma unroll
            for (int e = 0; e < 4; e++) acc[i][j][e] = 0.f;

    const int nk = K >> 5;

    {   // prologue: stage 0
        uint32_t sb = base;
#pragma unroll
        for (int j = 0; j < 4; j++) {
            cp16(sb + OF_AH + dOff[j], Ah + aOff[j]);
            if (ASPLIT) cp16(sb + OF_AL + dOff[j], Al + aOff[j]);
            cp16(sb + OF_BH + dOff[j], Bh + bOff[j]);
            if (BSPLIT) cp16(sb + OF_BL + dOff[j], Bl + bOff[j]);
        }
        cp_commit();
    }

    for (int i = 0; i < nk; i++) {
        cp_wait<0>();
        __syncthreads();

        if (i + 1 < nk) {
            uint32_t sb = base + (uint32_t)((i + 1) & 1) * STG_SZ;
            long long k0 = (long long)(i + 1) * 32;
#pragma unroll
            for (int j = 0; j < 4; j++) {
                cp16(sb + OF_AH + dOff[j], Ah + aOff[j] + k0);
                if (ASPLIT) cp16(sb + OF_AL + dOff[j], Al + aOff[j] + k0);
                cp16(sb + OF_BH + dOff[j], Bh + bOff[j] + k0);
                if (BSPLIT) cp16(sb + OF_BL + dOff[j], Bl + bOff[j] + k0);
            }
            cp_commit();
        }

        const uint32_t sb = base + (uint32_t)(i & 1) * STG_SZ;
#pragma unroll
        for (int ks = 0; ks < 2; ks++) {
            const uint32_t kb = (uint32_t)ks * 32u;
            uint32_t ah[4][4], al[4][4], bh[4][4], bl[4][4];
#pragma unroll
            for (int mf = 0; mf < 4; mf++) {
                uint32_t ro = (uint32_t)(m0 + mf * 16) * PITCH + kb + aLane;
                ldm_x4(ah[mf], sb + OF_AH + ro);
                if (ASPLIT) ldm_x4(al[mf], sb + OF_AL + ro);
            }
#pragma unroll
            for (int q = 0; q < 4; q++) {
                uint32_t ro = (uint32_t)(n0 + q * 16) * PITCH + kb + bLane;
                ldm_x4(bh[q], sb + OF_BH + ro);
                if (BSPLIT) ldm_x4(bl[q], sb + OF_BL + ro);
            }
#pragma unroll
            for (int mf = 0; mf < 4; mf++)
#pragma unroll
                for (int nf = 0; nf < 8; nf++) {
                    const int q = nf >> 1, h = (nf & 1) * 2;
                    mma16816(acc[mf][nf], ah[mf], bh[q][h], bh[q][h + 1]);
                    if (ASPLIT) mma16816(acc[mf][nf], al[mf], bh[q][h], bh[q][h + 1]);
                    if (BSPLIT) mma16816(acc[mf][nf], ah[mf], bl[q][h], bl[q][h + 1]);
                }
        }
    }

    // ---- epilogue (register-only; cross-tile smem safety via caller sync) ----
    const int tg = lane >> 2, tl = lane & 3;
#pragma unroll
    for (int mf = 0; mf < 4; mf++) {
#pragma unroll
        for (int nf = 0; nf < 8; nf++) {
            const int col = col0 + n0 + nf * 8 + tl * 2;
            float b0 = 0.f, b1 = 0.f;
            if (HASBIAS) { b0 = __ldg(bias + col); b1 = __ldg(bias + col + 1); }
#pragma unroll
            for (int hrow = 0; hrow < 2; hrow++) {
                const int row = row0 + m0 + mf * 16 + tg + hrow * 8;
                float v0 = acc[mf][nf][hrow * 2 + 0] * alpha + b0;
                float v1 = acc[mf][nf][hrow * 2 + 1] * alpha + b1;
                const long long off = cOff + (long long)row * N + col;
                if (WF32) {
                    float2 o; o.x = v0; o.y = v1;
                    *(float2*)(Cf + off) = o;
                } else {
                    __half h0 = __float2half_rn(v0);
                    __half h1 = __float2half_rn(v1);
                    __half2 th; th.x = h0; th.y = h1;
                    *(__half2*)(Chi + off) = th;
                    if (WLO) {
                        __half2 tlh;
                        tlh.x = __float2half_rn(v0 - __half2float(h0));
                        tlh.y = __float2half_rn(v1 - __half2float(h1));
                        *(__half2*)(Clo + off) = tlh;
                    }
                }
            }
        }
    }
}

// ---------------- persistent GEMM: grid-stride over (ntz, nty, ntx) tiles ---
template <bool ASPLIT, bool BSPLIT, bool WF32, bool HASBIAS, bool WLO>
__global__ void __launch_bounds__(128) mma_gemm_p(
    const __half* __restrict__ Ah_g, const __half* __restrict__ Al_g,
    const __half* __restrict__ Bh_g, const __half* __restrict__ Bl_g,
    const float* __restrict__ bias,
    float* __restrict__ Cf, __half* __restrict__ Chi, __half* __restrict__ Clo,
    int N, int K, float alpha,
    long long sA, long long sB, long long sC,
    int ntx, int nty, int ntz)
{
    const int total = ntx * nty * ntz;
    const int nxy = ntx * nty;
    for (int t = blockIdx.x; t < total; t += gridDim.x) {
        const int tz = t / nxy;
        const int r = t - tz * nxy;
        const int ty = r / ntx;
        const int tx = r - ty * ntx;
        __syncthreads();   // previous tile's smem reads complete before refill
        gemm_core<ASPLIT, BSPLIT, WF32, HASBIAS, WLO>(
            Ah_g + (long long)tz * sA, ASPLIT ? (Al_g + (long long)tz * sA) : nullptr,
            Bh_g + (long long)tz * sB, BSPLIT ? (Bl_g + (long long)tz * sB) : nullptr,
            bias, Cf, Chi, Clo, N, K, alpha,
            ty * 128, tx * 128, (long long)tz * sC);
    }
}

// persistent fused q/k/v projection: z in {0:q,1:k} 3-term; {2:v} 2-term
__global__ void __launch_bounds__(128) qkv_gemm_p(
    const __half* __restrict__ xhi, const __half* __restrict__ xlo,
    const __half* __restrict__ wThi, const __half* __restrict__ wTlo,
    const float* __restrict__ bq, const float* __restrict__ bk,
    const float* __restrict__ bv,
    __half* __restrict__ outhi, __half* __restrict__ outlo,
    int ntx, int nty)
{
    const int nxy = ntx * nty;
    const int total = 3 * nxy;
    for (int t = blockIdx.x; t < total; t += gridDim.x) {
        const int tz = t / nxy;
        const int r = t - tz * nxy;
        const int ty = r / ntx;
        const int tx = r - ty * ntx;
        const long long wOff = (long long)tz * DIM * DIM;
        __syncthreads();
        if (tz == 2) {
            gemm_core<false, true, false, true, false>(
                xhi, nullptr, wThi + wOff, wTlo + wOff, bv,
                nullptr, outhi, nullptr, DIM, DIM, 1.f,
                ty * 128, tx * 128, 2 * TD);
        } else {
            const float* bias = (tz == 0) ? bq : bk;
            gemm_core<true, true, false, true, true>(
                xhi, xlo, wThi + wOff, wTlo + wOff, bias,
                nullptr, outhi, outlo, DIM, DIM, 1.f,
                ty * 128, tx * 128, (long long)tz * TD);
        }
    }
}

// ============================================================================
// helper kernels
// ============================================================================
__global__ void __launch_bounds__(256) convert_split_kernel(
    const float* __restrict__ in, __half* __restrict__ hi,
    __half* __restrict__ lo, long long n4)
{
    long long i = (long long)blockIdx.x * 256 + threadIdx.x;
    if (i >= n4) return;
    float4 v = ((const float4*)in)[i];
    __half h0 = __float2half_rn(v.x), h1 = __float2half_rn(v.y);
    __half h2 = __float2half_rn(v.z), h3 = __float2half_rn(v.w);
    __half2 a, b; a.x = h0; a.y = h1; b.x = h2; b.y = h3;
    ((__half2*)hi)[i * 2 + 0] = a;
    ((__half2*)hi)[i * 2 + 1] = b;
    __half2 c, d;
    c.x = __float2half_rn(v.x - __half2float(h0));
    c.y = __float2half_rn(v.y - __half2float(h1));
    d.x = __float2half_rn(v.z - __half2float(h2));
    d.y = __float2half_rn(v.w - __half2float(h3));
    ((__half2*)lo)[i * 2 + 0] = c;
    ((__half2*)lo)[i * 2 + 1] = d;
}

__global__ void __launch_bounds__(256) transpose_split_kernel(
    const float* __restrict__ in, __half* __restrict__ hi,
    __half* __restrict__ lo, int R, int C)
{
    __shared__ float t[32][33];
    const int c0 = blockIdx.x * 32, r0 = blockIdx.y * 32;
    const int tx = threadIdx.x & 31, ty = threadIdx.x >> 5;
#pragma unroll
    for (int j = 0; j < 4; j++)
        t[ty + j * 8][tx] = in[(long long)(r0 + ty + j * 8) * C + c0 + tx];
    __syncthreads();
#pragma unroll
    for (int j = 0; j < 4; j++) {
        int oc = c0 + ty + j * 8;
        float v = t[tx][ty + j * 8];
        long long o = (long long)oc * R + r0 + tx;
        __half h = __float2half_rn(v);
        hi[o] = h;
        lo[o] = __float2half_rn(v - __half2float(h));
    }
}

__global__ void __launch_bounds__(256) transpose_half_kernel(
    const __half* __restrict__ in, __half* __restrict__ outp,
    int R, int C, long long sIn, long long sOut)
{
    __shared__ __half t[32][34];
    const __half* src = in + (long long)blockIdx.z * sIn;
    const int c0 = blockIdx.x * 32, r0 = blockIdx.y * 32;
    const int tx = threadIdx.x & 31, ty = threadIdx.x >> 5;
#pragma unroll
    for (int j = 0; j < 4; j++)
        t[ty + j * 8][tx] = src[(long long)(r0 + ty + j * 8) * C + c0 + tx];
    __syncthreads();
#pragma unroll
    for (int j = 0; j < 4; j++) {
        int oc = c0 + ty + j * 8;
        long long o = (long long)blockIdx.z * sOut + (long long)oc * R + r0 + tx;
        outp[o] = t[tx][ty + j * 8];
    }
}

__global__ void __launch_bounds__(256) softmax2048_kernel(
    float* __restrict__ p, __half* __restrict__ phi)
{
    const long long roff = (long long)blockIdx.x * 2048;
    float* row = p + roff;
    const int tid = threadIdx.x;

    float4 v0 = ((const float4*)row)[tid];
    float4 v1 = ((const float4*)row)[tid + 256];

    float m = fmaxf(fmaxf(fmaxf(v0.x, v0.y), fmaxf(v0.z, v0.w)),
                    fmaxf(fmaxf(v1.x, v1.y), fmaxf(v1.z, v1.w)));
    __shared__ float red[8];
#pragma unroll
    for (int o = 16; o; o >>= 1) m = fmaxf(m, __shfl_xor_sync(0xffffffffu, m, o));
    if ((tid & 31) == 0) red[tid >> 5] = m;
    __syncthreads();
    m = red[0];
#pragma unroll
    for (int i = 1; i < 8; i++) m = fmaxf(m, red[i]);
    __syncthreads();

    v0.x = expf(v0.x - m); v0.y = expf(v0.y - m);
    v0.z = expf(v0.z - m); v0.w = expf(v0.w - m);
    v1.x = expf(v1.x - m); v1.y = expf(v1.y - m);
    v1.z = expf(v1.z - m); v1.w = expf(v1.w - m);

    float s = (v0.x + v0.y) + (v0.z + v0.w) + (v1.x + v1.y) + (v1.z + v1.w);
#pragma unroll
    for (int o = 16; o; o >>= 1) s += __shfl_xor_sync(0xffffffffu, s, o);
    if ((tid & 31) == 0) red[tid >> 5] = s;
    __syncthreads();
    s = ((red[0] + red[1]) + (red[2] + red[3])) +
        ((red[4] + red[5]) + (red[6] + red[7]));
    float inv = 1.0f / s;

    v0.x *= inv; v0.y *= inv; v0.z *= inv; v0.w *= inv;
    v1.x *= inv; v1.y *= inv; v1.z *= inv; v1.w *= inv;

    ((float4*)row)[tid] = v0;
    ((float4*)row)[tid + 256] = v1;

    const float vv[8] = {v0.x, v0.y, v0.z, v0.w, v1.x, v1.y, v1.z, v1.w};
    const long long off[2] = {roff + (long long)tid * 4,
                              roff + (long long)(tid + 256) * 4};
#pragma unroll
    for (int hseg = 0; hseg < 2; hseg++) {
#pragma unroll
        for (int g = 0; g < 2; g++) {
            __half2 th;
            th.x = __float2half_rn(vv[hseg * 4 + g * 2]);
            th.y = __float2half_rn(vv[hseg * 4 + g * 2 + 1]);
            *(__half2*)(phi + off[hseg] + g * 2) = th;
        }
    }
}

// ============================================================================
// host launcher
// ============================================================================
extern "C" void kernel_launch(void* const* d_in, const int* in_sizes, int n_in,
                              void* d_out, int out_size)
{
    const float* x  = (const float*)d_in[0];
    const float* wq = (const float*)d_in[1];
    const float* bq = (const float*)d_in[2];
    const float* wk = (const float*)d_in[3];
    const float* bk = (const float*)d_in[4];
    const float* wv = (const float*)d_in[5];
    const float* bv = (const float*)d_in[6];
    const float* wp = (const float*)d_in[7];
    const float* bp = (const float*)d_in[8];
    float* out = (float*)d_out;

#define SYM(p, s) void* p##_; cudaGetSymbolAddress(&p##_, s);
    SYM(xhi, g_xhi) SYM(xlo, g_xlo)
    SYM(wth, g_wThi) SYM(wtl, g_wTlo)
    SYM(wph, g_wpThi) SYM(wpl, g_wpTlo)
    SYM(qkvh, g_qkvhi) SYM(qkvl, g_qkvlo)
    SYM(vth, g_vThi)
    SYM(phi, g_phi)
    SYM(cxh, g_ctxhi)
    SYM(sfb, g_scores_fb)
#undef SYM
#define HF(p) ((__half*)p##_)

    float* pattn = (out_size >= (long long)(OUT_ELEMS + PATTN_ELEMS))
                       ? (out + OUT_ELEMS) : (float*)sfb_;

    static int nPersist = 0;
    if (nPersist == 0) {
        int nsm = 148;
        cudaDeviceGetAttribute(&nsm, cudaDevAttrMultiProcessorCount, 0);
        nPersist = 2 * nsm;
    }

    cudaFuncSetAttribute(qkv_gemm_p, cudaFuncAttributeMaxDynamicSharedMemorySize, SMEM_DYN);
    cudaFuncSetAttribute(mma_gemm_p<true,  true,  true,  false, false>, cudaFuncAttributeMaxDynamicSharedMemorySize, SMEM_DYN);
    cudaFuncSetAttribute(mma_gemm_p<false, false, false, false, false>, cudaFuncAttributeMaxDynamicSharedMemorySize, SMEM_DYN);
    cudaFuncSetAttribute(mma_gemm_p<false, true,  true,  true,  false>, cudaFuncAttributeMaxDynamicSharedMemorySize, SMEM_DYN);

    // 1) split x
    convert_split_kernel<<<(TOK * DIM / 4 + 255) / 256, 256>>>(
        x, HF(xhi), HF(xlo), TOK * DIM / 4);

    // 2) transpose + split weights
    dim3 gW(DIM / 32, DIM / 32, 1);
    transpose_split_kernel<<<gW, 256>>>(wq, HF(wth) + 0 * DIM * DIM, HF(wtl) + 0 * DIM * DIM, DIM, DIM);
    transpose_split_kernel<<<gW, 256>>>(wk, HF(wth) + 1 * DIM * DIM, HF(wtl) + 1 * DIM * DIM, DIM, DIM);
    transpose_split_kernel<<<gW, 256>>>(wv, HF(wth) + 2 * DIM * DIM, HF(wtl) + 2 * DIM * DIM, DIM, DIM);
    transpose_split_kernel<<<gW, 256>>>(wp, HF(wph), HF(wpl), DIM, DIM);

    // 3) fused q,k,v projections (persistent: 3*64*8 = 1536 tiles)
    qkv_gemm_p<<<nPersist, 128, SMEM_DYN>>>(
        HF(xhi), HF(xlo), HF(wth), HF(wtl), bq, bk, bv, HF(qkvh), HF(qkvl),
        DIM / 128, TOK / 128);

    const __half* qhi = HF(qkvh) + 0 * TD; const __half* qlo = HF(qkvl) + 0 * TD;
    const __half* khi = HF(qkvh) + 1 * TD; const __half* klo = HF(qkvl) + 1 * TD;
    const __half* vhi = HF(qkvh) + 2 * TD;

    // 4) transpose v (hi only) per batch -> vT[b][d][t]
    dim3 gVT(DIM / 32, SEQ / 32, BATCH);
    transpose_half_kernel<<<gVT, 256>>>(vhi, HF(vth), SEQ, DIM,
                                        (long long)SEQ * DIM, (long long)DIM * SEQ);

    // 5) scores = 32 * q @ k^T (3-term, persistent 16*16*4 = 1024 tiles)
    mma_gemm_p<true, true, true, false, false><<<nPersist, 128, SMEM_DYN>>>(
        qhi, qlo, khi, klo, nullptr, pattn, nullptr, nullptr,
        SEQ, DIM, 32.f,
        (long long)SEQ * DIM, (long long)SEQ * DIM, (long long)SEQ * SEQ,
        SEQ / 128, SEQ / 128, BATCH);

    // 6) softmax in place + fp16 p_hi
    softmax2048_kernel<<<TOK, 256>>>(pattn, HF(phi));

    // 7) ctx = p_hi @ v_hi (1-term, persistent 8*16*4 = 512 tiles)
    mma_gemm_p<false, false, false, false, false><<<nPersist, 128, SMEM_DYN>>>(
        HF(phi), nullptr, HF(vth), nullptr, nullptr, nullptr, HF(cxh), nullptr,
        DIM, SEQ, 1.f,
        (long long)SEQ * SEQ, (long long)DIM * SEQ, (long long)SEQ * DIM,
        DIM / 128, SEQ / 128, BATCH);

    // 8) out = ctx_hi @ (wp_hi + wp_lo) + bp (2-term, persistent 512 tiles)
    mma_gemm_p<false, true, true, true, false><<<nPersist, 128, SMEM_DYN>>>(
        HF(cxh), nullptr, HF(wph), HF(wpl), bp, out, nullptr, nullptr,
        DIM, DIM, 1.f, 0, 0, 0,
        DIM / 128, TOK / 128, 1);
}